// round 14
// baseline (speedup 1.0000x reference)
#include <cuda_runtime.h>
#include <cuda_bf16.h>
#include <cstdint>

#define BATCH 4
#define NPTS 8192
#define KNN 16
#define NP_TOTAL (BATCH * NPTS)

typedef unsigned long long ull;

#define NCH1 33   // conv1: 259 ch -> 33 chunks of 8 ch (64 f)
#define NCH2 17   // conv2: 131 ch -> 17 chunks
#define ROWW 40   // A/B row stride in words (80 bf16 = 160B)
#define WSTR 132  // s_w row stride in floats
#define BCHUNK_WORDS 10240  // B chunk: 2 halves x 128 rows x 40 words
#define ACHUNK_WORDS 5120   // A chunk (64 rows): hi 2560 | lo 2560

__device__ float g_fcat1[NP_TOTAL * 260];   // [p][256 feat | 3 xyz | pad]
__device__ float g_fcat2[NP_TOTAL * 132];   // [p][128 feat | 3 xyz | pad]
__device__ float g_f2[NP_TOTAL * 128];
__device__ uint32_t g_B1[NCH1 * BCHUNK_WORDS];
__device__ uint32_t g_B2[NCH2 * BCHUNK_WORDS];
__device__ float g_w1t[128 * 128];
__device__ float g_w2t[128 * 64];

__device__ __forceinline__ float lrelu(float v) { return v >= 0.f ? v : 0.1f * v; }
__device__ __forceinline__ ull ffma2(ull a, ull b, ull c) {
    ull d; asm("fma.rn.f32x2 %0, %1, %2, %3;" : "=l"(d) : "l"(a), "l"(b), "l"(c)); return d;
}
__device__ __forceinline__ ull addf2(ull a, ull b) {
    ull d; asm("add.rn.f32x2 %0, %1, %2;" : "=l"(d) : "l"(a), "l"(b)); return d;
}
__device__ __forceinline__ ull dup2(float x) {
    ull d; asm("mov.b64 %0, {%1, %1};" : "=l"(d) : "f"(x)); return d;
}
__device__ __forceinline__ float2 unpk(ull v) {
    float2 r; asm("mov.b64 {%0, %1}, %2;" : "=f"(r.x), "=f"(r.y) : "l"(v)); return r;
}
__device__ __forceinline__ uint32_t pack_bf16(float a, float b) {
    __nv_bfloat162 h = __floats2bfloat162_rn(a, b);
    return *(uint32_t*)&h;
}
__device__ __forceinline__ float bf16r(float x) {
    return __bfloat162float(__float2bfloat16_rn(x));
}
__device__ __forceinline__ uint32_t s2u(const void* p) {
    uint32_t a;
    asm("{ .reg .u64 t; cvta.to.shared.u64 t, %1; cvt.u32.u64 %0, t; }" : "=r"(a) : "l"(p));
    return a;
}
__device__ __forceinline__ void cp16(uint32_t dst, const void* src) {
    asm volatile("cp.async.cg.shared.global [%0], [%1], 16;" :: "r"(dst), "l"(src));
}
#define NBAR_SYNC(id, cnt)   asm volatile("bar.sync %0, %1;"   :: "r"(id), "r"(cnt) : "memory")
#define NBAR_ARRIVE(id, cnt) asm volatile("bar.arrive %0, %1;" :: "r"(id), "r"(cnt) : "memory")

__device__ __forceinline__ void mma_bf16(float* c, uint32_t a0, uint32_t a1,
                                         uint32_t a2, uint32_t a3,
                                         uint32_t b0, uint32_t b1) {
    asm volatile(
        "mma.sync.aligned.m16n8k16.row.col.f32.bf16.bf16.f32 "
        "{%0,%1,%2,%3}, {%4,%5,%6,%7}, {%8,%9}, {%0,%1,%2,%3};"
        : "+f"(c[0]), "+f"(c[1]), "+f"(c[2]), "+f"(c[3])
        : "r"(a0), "r"(a1), "r"(a2), "r"(a3), "r"(b0), "r"(b1));
}

// ---------------- transpose -------------------------------------------------------
__global__ void transpose_feat(const float* __restrict__ feat) {
    __shared__ float tile[32][33];
    int b = blockIdx.z;
    int n0 = blockIdx.x * 32, c0 = blockIdx.y * 32;
    int x = threadIdx.x, y = threadIdx.y;
    tile[y][x] = feat[((size_t)b * 256 + c0 + y) * NPTS + n0 + x];
    __syncthreads();
    g_fcat1[((size_t)(b * NPTS + n0 + y)) * 260 + c0 + x] = tile[x][y];
}

// col layout per k16 sub: pos(k) = (k&1) | (((k>>1)&3)<<2) | (((k>>3)&1)<<1)
__device__ __forceinline__ float fetch_w(const float* wl, int Freal, int CIN, int n,
                                         int ci, int col) {
    if (col >= 64) return 0.f;
    int s = col >> 4, pos = col & 15;
    int k = (pos & 1) | (((pos >> 2) & 3) << 1) | (((pos >> 1) & 1) << 3);
    int f = ci * 64 + s * 16 + k;
    int c = f >> 3, m = f & 7;
    if (c >= CIN + 3) return 0.f;
    int co = (c < CIN) ? c + 3 : c - CIN;
    return wl[n * Freal + co * 8 + m];
}

// ---------------- merged prep -----------------------------------------------------
__global__ void prep_all(const float* __restrict__ xyz,
                         const float* __restrict__ wl1, const float* __restrict__ wl2,
                         const float* __restrict__ wm1, const float* __restrict__ wm2) {
    int i = blockIdx.x * blockDim.x + threadIdx.x;
    if (i < 128 * 128) { int c = i >> 7, o = i & 127; g_w1t[i] = wm1[o * 128 + c]; }
    if (i < 128 * 64)  { int o = i >> 6, j = i & 63;  g_w2t[i] = wm2[j * 128 + o]; }
    if (i < NP_TOTAL * 3) {
        int p = i / 3, d = i - p * 3;
        int b = p >> 13, n = p & (NPTS - 1);
        float v = xyz[((size_t)b * 3 + d) * NPTS + n];
        g_fcat1[(size_t)p * 260 + 256 + d] = v;
        g_fcat2[(size_t)p * 132 + 128 + d] = v;
        if (d == 0) {
            g_fcat1[(size_t)p * 260 + 259] = 0.f;
            g_fcat2[(size_t)p * 132 + 131] = 0.f;
        }
    }
    if (i < NCH1 * BCHUNK_WORDS) {
        int ci = i / BCHUNK_WORDS, r = i % BCHUNK_WORDS;
        int h = r / 5120, r2 = r % 5120;
        int n = r2 / ROWW, wc = r2 % ROWW;
        float v0 = fetch_w(wl1, 2072, 256, n, ci, 2 * wc);
        float v1 = fetch_w(wl1, 2072, 256, n, ci, 2 * wc + 1);
        float h0 = bf16r(v0), h1 = bf16r(v1);
        g_B1[i] = h ? pack_bf16(v0 - h0, v1 - h1) : pack_bf16(h0, h1);
    }
    if (i < NCH2 * BCHUNK_WORDS) {
        int ci = i / BCHUNK_WORDS, r = i % BCHUNK_WORDS;
        int h = r / 5120, r2 = r % 5120;
        int n = r2 / ROWW, wc = r2 % ROWW;
        float v0 = fetch_w(wl2, 1048, 128, n, ci, 2 * wc);
        float v1 = fetch_w(wl2, 1048, 128, n, ci, 2 * wc + 1);
        float h0 = bf16r(v0), h1 = bf16r(v1);
        g_B2[i] = h ? pack_bf16(v0 - h0, v1 - h1) : pack_bf16(h0, h1);
    }
}

// ---------------- fused warp-specialized conv --------------------------------------
// CTA: 512 threads. Warps 0-7: MMA (M=64 x N=128). Warps 8-15: producers
// (k-split gather + weight-net contraction + shfl reduce -> A smem double buffer).
#define F_OFF_A    0                    // 2 x 5120
#define F_OFF_B    10240                // 2 x 10240
#define F_OFF_W    30720                // 64*132 = 8448
#define F_OFF_NBR  39168                // 1024 ints
#define F_OFF_CX   40192                // 192
#define F_OFF_BIAS 40384                // 128
#define F_DYN_WORDS 40512
#define F_DYN_BYTES (F_DYN_WORDS * 4)   // 162048

template <int CIN, int STRIDE_IN, int OUT_STRIDE, int NCHUNK>
__global__ void __launch_bounds__(512, 1)
conv_fused(const float* __restrict__ fcat, const int* __restrict__ knn,
           const float* __restrict__ w_wn, const float* __restrict__ b_wn,
           const float* __restrict__ b_lin, const uint32_t* __restrict__ gB,
           float* __restrict__ out) {
    constexpr int CIN3 = CIN + 3;

    extern __shared__ float dyn[];
    uint32_t* smw = (uint32_t*)dyn;
    float* s_w    = dyn + F_OFF_W;
    int*   s_nbr  = (int*)(dyn + F_OFF_NBR);
    float* s_cx   = dyn + F_OFF_CX;
    float* s_bias = dyn + F_OFF_BIAS;

    __shared__ float s_wn[24];
    __shared__ float s_bwn[8];

    const int tid  = threadIdx.x;
    const int wid  = tid >> 5, lane = tid & 31;
    const int base = blockIdx.x * 64;
    const int boff = (base >> 13) << 13;

    // ---- prologue: all 512 threads
    if (tid < 24) s_wn[tid] = w_wn[tid];
    if (tid < 8)  s_bwn[tid] = b_wn[tid];
    if (tid < 128) s_bias[tid] = b_lin[tid];
    if (tid < 192) {
        int pt = tid / 3, d = tid - pt * 3;
        s_cx[pt * 3 + d] = fcat[(size_t)(base + pt) * STRIDE_IN + CIN + d];
    }
    for (int id = tid; id < 1024; id += 512) {
        int pt = id >> 4, k = id & 15;
        s_nbr[id] = boff + knn[(size_t)(base + pt) * KNN + k];
    }
    __syncthreads();
    for (int id = tid; id < 1024; id += 512) {
        int pt = id >> 4, k = id & 15;
        int j = s_nbr[id];
        const float* nx = fcat + (size_t)j * STRIDE_IN + CIN;
        float px = nx[0] - s_cx[pt * 3 + 0];
        float py = nx[1] - s_cx[pt * 3 + 1];
        float pz = nx[2] - s_cx[pt * 3 + 2];
#pragma unroll
        for (int m = 0; m < 8; ++m) {
            float v = s_wn[m * 3 + 0] * px + s_wn[m * 3 + 1] * py +
                      s_wn[m * 3 + 2] * pz + s_bwn[m];
            s_w[pt * WSTR + k * 8 + m] = lrelu(v);
        }
    }
    __syncthreads();

    if (wid >= 8) {
        // ================= producer warps (8-15), 256 threads =================
        // thread -> (pt, quad, khalf): pt = t>>2, quad = (t>>1)&1, khalf = t&1
        const int t = tid - 256;
        const int pt_p  = t >> 2;
        const int quad  = (t >> 1) & 1;
        const int khalf = t & 1;
        int nb[8];
        {
            const int4* q = (const int4*)(s_nbr + pt_p * 16 + khalf * 8);
            int4 n0 = q[0], n1 = q[1];
            nb[0]=n0.x; nb[1]=n0.y; nb[2]=n0.z; nb[3]=n0.w;
            nb[4]=n1.x; nb[5]=n1.y; nb[6]=n1.z; nb[7]=n1.w;
        }
        const float* wp_p = s_w + pt_p * WSTR + khalf * 64;

        for (int ci = 0; ci < NCHUNK; ++ci) {
            const int b = ci & 1;
            if (ci >= 2) NBAR_SYNC(3 + b, 512);

            const int cbase = ci * 8 + quad * 4;
            ull pa[16];
#pragma unroll
            for (int i = 0; i < 16; ++i) pa[i] = 0ULL;
            if (cbase < CIN3) {
                const float* fp = fcat + cbase;
#pragma unroll
                for (int k = 0; k < 8; ++k) {
                    float4 f4 = __ldg((const float4*)(fp + (size_t)nb[k] * STRIDE_IN));
                    ulonglong2 w01 = *(const ulonglong2*)(wp_p + k * 8);
                    ulonglong2 w23 = *(const ulonglong2*)(wp_p + k * 8 + 4);
                    ull f0 = dup2(f4.x), f1 = dup2(f4.y), f2 = dup2(f4.z), f3 = dup2(f4.w);
                    pa[0]  = ffma2(f0, w01.x, pa[0]);
                    pa[1]  = ffma2(f0, w01.y, pa[1]);
                    pa[2]  = ffma2(f0, w23.x, pa[2]);
                    pa[3]  = ffma2(f0, w23.y, pa[3]);
                    pa[4]  = ffma2(f1, w01.x, pa[4]);
                    pa[5]  = ffma2(f1, w01.y, pa[5]);
                    pa[6]  = ffma2(f1, w23.x, pa[6]);
                    pa[7]  = ffma2(f1, w23.y, pa[7]);
                    pa[8]  = ffma2(f2, w01.x, pa[8]);
                    pa[9]  = ffma2(f2, w01.y, pa[9]);
                    pa[10] = ffma2(f2, w23.x, pa[10]);
                    pa[11] = ffma2(f2, w23.y, pa[11]);
                    pa[12] = ffma2(f3, w01.x, pa[12]);
                    pa[13] = ffma2(f3, w01.y, pa[13]);
                    pa[14] = ffma2(f3, w23.x, pa[14]);
                    pa[15] = ffma2(f3, w23.y, pa[15]);
                }
            }
            // combine k-halves: partner lane differs in bit 0
#pragma unroll
            for (int i = 0; i < 16; ++i) {
                ull o = __shfl_xor_sync(0xFFFFFFFFu, pa[i], 1);
                pa[i] = addf2(pa[i], o);
            }

            uint32_t* abuf = smw + F_OFF_A + b * ACHUNK_WORDS;
            uint32_t* dst = abuf + pt_p * ROWW + quad * 16 + khalf * 2560; // hi or lo block
            uint32_t w16[16];
            if (khalf == 0) {
#pragma unroll
                for (int g2 = 0; g2 < 2; ++g2) {
#pragma unroll
                    for (int mp = 0; mp < 4; ++mp) {
                        float2 va = unpk(pa[g2 * 8 + mp]);
                        float2 vb = unpk(pa[g2 * 8 + 4 + mp]);
                        w16[g2 * 8 + mp * 2 + 0] = pack_bf16(bf16r(va.x), bf16r(va.y));
                        w16[g2 * 8 + mp * 2 + 1] = pack_bf16(bf16r(vb.x), bf16r(vb.y));
                    }
                }
            } else {
#pragma unroll
                for (int g2 = 0; g2 < 2; ++g2) {
#pragma unroll
                    for (int mp = 0; mp < 4; ++mp) {
                        float2 va = unpk(pa[g2 * 8 + mp]);
                        float2 vb = unpk(pa[g2 * 8 + 4 + mp]);
                        w16[g2 * 8 + mp * 2 + 0] =
                            pack_bf16(va.x - bf16r(va.x), va.y - bf16r(va.y));
                        w16[g2 * 8 + mp * 2 + 1] =
                            pack_bf16(vb.x - bf16r(vb.x), vb.y - bf16r(vb.y));
                    }
                }
            }
            ((uint4*)dst)[0] = ((uint4*)w16)[0];
            ((uint4*)dst)[1] = ((uint4*)w16)[1];
            ((uint4*)dst)[2] = ((uint4*)w16)[2];
            ((uint4*)dst)[3] = ((uint4*)w16)[3];

            __threadfence_block();
            NBAR_ARRIVE(1 + b, 512);
        }
    } else {
        // ================= MMA warps (0-7), 256 threads =================
        const int g = lane >> 2, t = lane & 3;
        const int rt = wid & 1, ch = wid >> 1;
        const int rowA = rt * 32 + g;

        auto copy_B = [&](int ci, int bsel) {
            const uint4* srcB = (const uint4*)(gB + (size_t)ci * BCHUNK_WORDS);
            const uint32_t dB = s2u(smw + F_OFF_B + bsel * BCHUNK_WORDS);
#pragma unroll
            for (int r = 0; r < 10; ++r) {
                int i = tid + r * 256;
                cp16(dB + i * 16, srcB + i);
            }
            asm volatile("cp.async.commit_group;");
        };

        copy_B(0, 0);

        float acc[32];
#pragma unroll
        for (int i = 0; i < 32; ++i) acc[i] = 0.f;

        for (int ci = 0; ci < NCHUNK; ++ci) {
            const int b = ci & 1;
            asm volatile("cp.async.wait_group 0;");
            NBAR_SYNC(1 + b, 512);
            if (ci + 1 < NCHUNK) copy_B(ci + 1, b ^ 1);

            const uint32_t* sAH = smw + F_OFF_A + b * ACHUNK_WORDS;
            const uint32_t* sAL = sAH + 2560;
            const uint32_t* sB  = smw + F_OFF_B + b * BCHUNK_WORDS;
#pragma unroll
            for (int s = 0; s < 4; ++s) {
                const int off = s * 8 + 2 * t;
                uint2 ah0 = *(const uint2*)(sAH + (rowA)      * ROWW + off);
                uint2 ah1 = *(const uint2*)(sAH + (rowA + 8)  * ROWW + off);
                uint2 ah2 = *(const uint2*)(sAH + (rowA + 16) * ROWW + off);
                uint2 ah3 = *(const uint2*)(sAH + (rowA + 24) * ROWW + off);
                uint2 al0 = *(const uint2*)(sAL + (rowA)      * ROWW + off);
                uint2 al1 = *(const uint2*)(sAL + (rowA + 8)  * ROWW + off);
                uint2 al2 = *(const uint2*)(sAL + (rowA + 16) * ROWW + off);
                uint2 al3 = *(const uint2*)(sAL + (rowA + 24) * ROWW + off);
                uint2 bh[4], bl[4];
#pragma unroll
                for (int nt = 0; nt < 4; ++nt) {
                    const int brow = ch * 32 + nt * 8 + g;
                    bh[nt] = *(const uint2*)(sB + brow * ROWW + off);
                    bl[nt] = *(const uint2*)(sB + 5120 + brow * ROWW + off);
                }
#pragma unroll
                for (int nt = 0; nt < 4; ++nt) {
                    mma_bf16(acc + nt * 4,      ah0.x, ah1.x, ah0.y, ah1.y, bh[nt].x, bh[nt].y);
                    mma_bf16(acc + 16 + nt * 4, ah2.x, ah3.x, ah2.y, ah3.y, bh[nt].x, bh[nt].y);
                }
#pragma unroll
                for (int nt = 0; nt < 4; ++nt) {
                    mma_bf16(acc + nt * 4,      ah0.x, ah1.x, ah0.y, ah1.y, bl[nt].x, bl[nt].y);
                    mma_bf16(acc + 16 + nt * 4, ah2.x, ah3.x, ah2.y, ah3.y, bl[nt].x, bl[nt].y);
                }
#pragma unroll
                for (int nt = 0; nt < 4; ++nt) {
                    mma_bf16(acc + nt * 4,      al0.x, al1.x, al0.y, al1.y, bh[nt].x, bh[nt].y);
                    mma_bf16(acc + 16 + nt * 4, al2.x, al3.x, al2.y, al3.y, bh[nt].x, bh[nt].y);
                }
            }
            NBAR_ARRIVE(3 + b, 512);
        }

        // epilogue: bias + leaky
#pragma unroll
        for (int mt = 0; mt < 2; ++mt) {
            const int r0 = base + rt * 32 + mt * 16 + g;
#pragma unroll
            for (int nt = 0; nt < 4; ++nt) {
                const int col = ch * 32 + nt * 8 + 2 * t;
                float b0 = s_bias[col], b1 = s_bias[col + 1];
                const float* C = acc + mt * 16 + nt * 4;
                float2 r01 = make_float2(lrelu(C[0] + b0), lrelu(C[1] + b1));
                float2 r23 = make_float2(lrelu(C[2] + b0), lrelu(C[3] + b1));
                *(float2*)(out + (size_t)r0 * OUT_STRIDE + col) = r01;
                *(float2*)(out + (size_t)(r0 + 8) * OUT_STRIDE + col) = r23;
            }
        }
    }
}

// ---------------- MLP head ----------------------------------------------------------
__global__ void mlp_kernel(const float* __restrict__ w_last, const float* __restrict__ b1,
                           const float* __restrict__ b2, const float* __restrict__ blast,
                           float* __restrict__ out) {
    __shared__ float s_f[16 * 128];
    __shared__ float s_h1[16 * 128];
    __shared__ float s_h2[16 * 64];
    const int tid = threadIdx.x;
    const int p0  = blockIdx.x * 16;

    for (int i = tid; i < 16 * 128; i += 256) s_f[i] = g_f2[(size_t)p0 * 128 + i];
    __syncthreads();
    {
        int o = tid & 127, tg = tid >> 7;
        float acc[8];
#pragma unroll
        for (int i = 0; i < 8; ++i) acc[i] = 0.f;
        for (int c = 0; c < 128; ++c) {
            float wv = g_w1t[c * 128 + o];
#pragma unroll
            for (int i = 0; i < 8; ++i) acc[i] += s_f[(tg * 8 + i) * 128 + c] * wv;
        }
        float bb = b1[o];
#pragma unroll
        for (int i = 0; i < 8; ++i) s_h1[(tg * 8 + i) * 128 + o] = lrelu(acc[i] + bb);
    }
    __syncthreads();
    {
        int jj = tid & 63, tg = tid >> 6;
        float acc[4];
#pragma unroll
        for (int i = 0; i < 4; ++i) acc[i] = 0.f;
        for (int c = 0; c < 128; ++c) {
            float wv = g_w2t[c * 64 + jj];
#pragma unroll
            for (int i = 0; i < 4; ++i) acc[i] += s_h1[(tg * 4 + i) * 128 + c] * wv;
        }
        float bb = b2[jj];
#pragma unroll
        for (int i = 0; i < 4; ++i) s_h2[(tg * 4 + i) * 64 + jj] = lrelu(acc[i] + bb);
    }
    __syncthreads();

    const int b = p0 >> 13, n0 = p0 & (NPTS - 1);
    for (int i = tid; i < 16 * 64; i += 256) {
        int t2 = i & 15, jj = i >> 4;
        out[((size_t)(b * 64 + jj)) * NPTS + n0 + t2] = s_h2[t2 * 64 + jj];
    }
    if (tid < 48) {
        int t2 = tid & 15, d = tid >> 4;
        float acc = 0.f;
#pragma unroll 8
        for (int jj = 0; jj < 64; ++jj) acc += w_last[d * 64 + jj] * s_h2[t2 * 64 + jj];
        out[(size_t)BATCH * 64 * NPTS + ((size_t)(b * 3 + d)) * NPTS + n0 + t2] = acc + blast[d];
    }
}

// ---------------- launch --------------------------------------------------------------
extern "C" void kernel_launch(void* const* d_in, const int* in_sizes, int n_in,
                              void* d_out, int out_size) {
    const float* xyz    = (const float*)d_in[0];
    const float* feat   = (const float*)d_in[1];
    const int*   knn    = (const int*)d_in[2];
    const float* w_wn1  = (const float*)d_in[3];
    const float* b_wn1  = (const float*)d_in[4];
    const float* w_lin1 = (const float*)d_in[5];
    const float* b_lin1 = (const float*)d_in[6];
    const float* w_wn2  = (const float*)d_in[7];
    const float* b_wn2  = (const float*)d_in[8];
    const float* w_lin2 = (const float*)d_in[9];
    const float* b_lin2 = (const float*)d_in[10];
    const float* w_mlp1 = (const float*)d_in[11];
    const float* b_mlp1 = (const float*)d_in[12];
    const float* w_mlp2 = (const float*)d_in[13];
    const float* b_mlp2 = (const float*)d_in[14];
    const float* w_last = (const float*)d_in[15];
    const float* b_last = (const float*)d_in[16];
    float* out = (float*)d_out;

    void *p_fcat1, *p_fcat2, *p_f2, *p_B1, *p_B2;
    cudaGetSymbolAddress(&p_fcat1, g_fcat1);
    cudaGetSymbolAddress(&p_fcat2, g_fcat2);
    cudaGetSymbolAddress(&p_f2, g_f2);
    cudaGetSymbolAddress(&p_B1, g_B1);
    cudaGetSymbolAddress(&p_B2, g_B2);

    {
        dim3 tb(32, 32);
        dim3 tg(NPTS / 32, 256 / 32, BATCH);
        transpose_feat<<<tg, tb>>>(feat);
    }
    prep_all<<<(NCH1 * BCHUNK_WORDS + 255) / 256, 256>>>(xyz, w_lin1, w_lin2, w_mlp1, w_mlp2);

    cudaFuncSetAttribute(conv_fused<256, 260, 132, NCH1>,
                         cudaFuncAttributeMaxDynamicSharedMemorySize, F_DYN_BYTES);
    conv_fused<256, 260, 132, NCH1><<<NP_TOTAL / 64, 512, F_DYN_BYTES>>>(
        (const float*)p_fcat1, knn, w_wn1, b_wn1, b_lin1, (const uint32_t*)p_B1,
        (float*)p_fcat2);

    cudaFuncSetAttribute(conv_fused<128, 132, 128, NCH2>,
                         cudaFuncAttributeMaxDynamicSharedMemorySize, F_DYN_BYTES);
    conv_fused<128, 132, 128, NCH2><<<NP_TOTAL / 64, 512, F_DYN_BYTES>>>(
        (const float*)p_fcat2, knn, w_wn2, b_wn2, b_lin2, (const uint32_t*)p_B2,
        (float*)p_f2);

    mlp_kernel<<<NP_TOTAL / 16, 256>>>(w_last, b_mlp1, b_mlp2, b_last, out);
}

// round 15
// speedup vs baseline: 1.1078x; 1.1078x over previous
#include <cuda_runtime.h>
#include <cuda_bf16.h>
#include <cstdint>

#define BATCH 4
#define NPTS 8192
#define KNN 16
#define NP_TOTAL (BATCH * NPTS)

typedef unsigned long long ull;

#define NCH1 33   // conv1: 259 ch -> 33 chunks of 8 ch (64 f)
#define NCH2 17   // conv2: 131 ch -> 17 chunks
#define ROWW 40   // A/B row stride in words (80 bf16 = 160B)
#define WSTR 132  // s_w row stride in floats
#define BCHUNK_WORDS 10240  // B chunk: 2 halves x 128 rows x 40 words
#define ACHUNK_WORDS 5120   // A chunk (64 rows): hi 2560 | lo 2560

__device__ float g_fcat1[NP_TOTAL * 260];   // [p][256 feat | 3 xyz | pad]
__device__ float g_fcat2[NP_TOTAL * 132];   // [p][128 feat | 3 xyz | pad]
__device__ float g_f2[NP_TOTAL * 128];
__device__ uint32_t g_B1[NCH1 * BCHUNK_WORDS];
__device__ uint32_t g_B2[NCH2 * BCHUNK_WORDS];
__device__ float g_w1t[128 * 128];
__device__ float g_w2t[128 * 64];

__device__ __forceinline__ float lrelu(float v) { return v >= 0.f ? v : 0.1f * v; }
__device__ __forceinline__ ull ffma2(ull a, ull b, ull c) {
    ull d; asm("fma.rn.f32x2 %0, %1, %2, %3;" : "=l"(d) : "l"(a), "l"(b), "l"(c)); return d;
}
__device__ __forceinline__ ull dup2(float x) {
    ull d; asm("mov.b64 %0, {%1, %1};" : "=l"(d) : "f"(x)); return d;
}
__device__ __forceinline__ float2 unpk(ull v) {
    float2 r; asm("mov.b64 {%0, %1}, %2;" : "=f"(r.x), "=f"(r.y) : "l"(v)); return r;
}
__device__ __forceinline__ uint32_t pack_bf16(float a, float b) {
    __nv_bfloat162 h = __floats2bfloat162_rn(a, b);
    return *(uint32_t*)&h;
}
__device__ __forceinline__ float bf16r(float x) {
    return __bfloat162float(__float2bfloat16_rn(x));
}
__device__ __forceinline__ uint32_t s2u(const void* p) {
    uint32_t a;
    asm("{ .reg .u64 t; cvta.to.shared.u64 t, %1; cvt.u32.u64 %0, t; }" : "=r"(a) : "l"(p));
    return a;
}
__device__ __forceinline__ void cp16(uint32_t dst, const void* src) {
    asm volatile("cp.async.cg.shared.global [%0], [%1], 16;" :: "r"(dst), "l"(src));
}
#define NBAR_SYNC(id, cnt)   asm volatile("bar.sync %0, %1;"   :: "r"(id), "r"(cnt) : "memory")
#define NBAR_ARRIVE(id, cnt) asm volatile("bar.arrive %0, %1;" :: "r"(id), "r"(cnt) : "memory")

__device__ __forceinline__ void mma_bf16(float* c, uint32_t a0, uint32_t a1,
                                         uint32_t a2, uint32_t a3,
                                         uint32_t b0, uint32_t b1) {
    asm volatile(
        "mma.sync.aligned.m16n8k16.row.col.f32.bf16.bf16.f32 "
        "{%0,%1,%2,%3}, {%4,%5,%6,%7}, {%8,%9}, {%0,%1,%2,%3};"
        : "+f"(c[0]), "+f"(c[1]), "+f"(c[2]), "+f"(c[3])
        : "r"(a0), "r"(a1), "r"(a2), "r"(a3), "r"(b0), "r"(b1));
}

// ---------------- transpose -------------------------------------------------------
__global__ void transpose_feat(const float* __restrict__ feat) {
    __shared__ float tile[32][33];
    int b = blockIdx.z;
    int n0 = blockIdx.x * 32, c0 = blockIdx.y * 32;
    int x = threadIdx.x, y = threadIdx.y;
    tile[y][x] = feat[((size_t)b * 256 + c0 + y) * NPTS + n0 + x];
    __syncthreads();
    g_fcat1[((size_t)(b * NPTS + n0 + y)) * 260 + c0 + x] = tile[x][y];
}

// col layout per k16 sub: pos(k) = (k&1) | (((k>>1)&3)<<2) | (((k>>3)&1)<<1)
__device__ __forceinline__ float fetch_w(const float* wl, int Freal, int CIN, int n,
                                         int ci, int col) {
    if (col >= 64) return 0.f;
    int s = col >> 4, pos = col & 15;
    int k = (pos & 1) | (((pos >> 2) & 3) << 1) | (((pos >> 1) & 1) << 3);
    int f = ci * 64 + s * 16 + k;
    int c = f >> 3, m = f & 7;
    if (c >= CIN + 3) return 0.f;
    int co = (c < CIN) ? c + 3 : c - CIN;
    return wl[n * Freal + co * 8 + m];
}

// ---------------- merged prep -----------------------------------------------------
__global__ void prep_all(const float* __restrict__ xyz,
                         const float* __restrict__ wl1, const float* __restrict__ wl2,
                         const float* __restrict__ wm1, const float* __restrict__ wm2) {
    int i = blockIdx.x * blockDim.x + threadIdx.x;
    if (i < 128 * 128) { int c = i >> 7, o = i & 127; g_w1t[i] = wm1[o * 128 + c]; }
    if (i < 128 * 64)  { int o = i >> 6, j = i & 63;  g_w2t[i] = wm2[j * 128 + o]; }
    if (i < NP_TOTAL * 3) {
        int p = i / 3, d = i - p * 3;
        int b = p >> 13, n = p & (NPTS - 1);
        float v = xyz[((size_t)b * 3 + d) * NPTS + n];
        g_fcat1[(size_t)p * 260 + 256 + d] = v;
        g_fcat2[(size_t)p * 132 + 128 + d] = v;
        if (d == 0) {
            g_fcat1[(size_t)p * 260 + 259] = 0.f;
            g_fcat2[(size_t)p * 132 + 131] = 0.f;
        }
    }
    if (i < NCH1 * BCHUNK_WORDS) {
        int ci = i / BCHUNK_WORDS, r = i % BCHUNK_WORDS;
        int h = r / 5120, r2 = r % 5120;
        int n = r2 / ROWW, wc = r2 % ROWW;
        float v0 = fetch_w(wl1, 2072, 256, n, ci, 2 * wc);
        float v1 = fetch_w(wl1, 2072, 256, n, ci, 2 * wc + 1);
        float h0 = bf16r(v0), h1 = bf16r(v1);
        g_B1[i] = h ? pack_bf16(v0 - h0, v1 - h1) : pack_bf16(h0, h1);
    }
    if (i < NCH2 * BCHUNK_WORDS) {
        int ci = i / BCHUNK_WORDS, r = i % BCHUNK_WORDS;
        int h = r / 5120, r2 = r % 5120;
        int n = r2 / ROWW, wc = r2 % ROWW;
        float v0 = fetch_w(wl2, 1048, 128, n, ci, 2 * wc);
        float v1 = fetch_w(wl2, 1048, 128, n, ci, 2 * wc + 1);
        float h0 = bf16r(v0), h1 = bf16r(v1);
        g_B2[i] = h ? pack_bf16(v0 - h0, v1 - h1) : pack_bf16(h0, h1);
    }
}

// ---------------- fused warp-specialized conv --------------------------------------
// CTA: 384 threads. Warps 0-7: MMA (M=64 x N=128, 32x32 warp tiles, register-
// pipelined fragment loads). Warps 8-11: producers -> A smem double buffer.
#define F_OFF_A    0                    // 2 x 5120
#define F_OFF_B    10240                // 2 x 10240
#define F_OFF_W    30720                // 64*132 = 8448
#define F_OFF_NBR  39168                // 1024 ints
#define F_OFF_CX   40192                // 192
#define F_OFF_BIAS 40384                // 128
#define F_DYN_WORDS 40512
#define F_DYN_BYTES (F_DYN_WORDS * 4)   // 162048

template <int CIN, int STRIDE_IN, int OUT_STRIDE, int NCHUNK>
__global__ void __launch_bounds__(384, 1)
conv_fused(const float* __restrict__ fcat, const int* __restrict__ knn,
           const float* __restrict__ w_wn, const float* __restrict__ b_wn,
           const float* __restrict__ b_lin, const uint32_t* __restrict__ gB,
           float* __restrict__ out) {
    constexpr int CIN3 = CIN + 3;

    extern __shared__ float dyn[];
    uint32_t* smw = (uint32_t*)dyn;
    float* s_w    = dyn + F_OFF_W;
    int*   s_nbr  = (int*)(dyn + F_OFF_NBR);
    float* s_cx   = dyn + F_OFF_CX;
    float* s_bias = dyn + F_OFF_BIAS;

    __shared__ float s_wn[24];
    __shared__ float s_bwn[8];

    const int tid  = threadIdx.x;
    const int wid  = tid >> 5, lane = tid & 31;
    const int base = blockIdx.x * 64;
    const int boff = (base >> 13) << 13;

    // ---- prologue: all 384 threads
    if (tid < 24) s_wn[tid] = w_wn[tid];
    if (tid < 8)  s_bwn[tid] = b_wn[tid];
    if (tid < 128) s_bias[tid] = b_lin[tid];
    if (tid < 192) {
        int pt = tid / 3, d = tid - pt * 3;
        s_cx[pt * 3 + d] = fcat[(size_t)(base + pt) * STRIDE_IN + CIN + d];
    }
    for (int id = tid; id < 1024; id += 384) {
        int pt = id >> 4, k = id & 15;
        s_nbr[id] = boff + knn[(size_t)(base + pt) * KNN + k];
    }
    __syncthreads();
    for (int id = tid; id < 1024; id += 384) {
        int pt = id >> 4, k = id & 15;
        int j = s_nbr[id];
        const float* nx = fcat + (size_t)j * STRIDE_IN + CIN;
        float px = nx[0] - s_cx[pt * 3 + 0];
        float py = nx[1] - s_cx[pt * 3 + 1];
        float pz = nx[2] - s_cx[pt * 3 + 2];
#pragma unroll
        for (int m = 0; m < 8; ++m) {
            float v = s_wn[m * 3 + 0] * px + s_wn[m * 3 + 1] * py +
                      s_wn[m * 3 + 2] * pz + s_bwn[m];
            s_w[pt * WSTR + k * 8 + m] = lrelu(v);
        }
    }
    __syncthreads();

    if (wid >= 8) {
        // ================= producer warps (8-11), 128 threads =================
        const int ptl  = lane >> 1;
        const int pt_p = (wid - 8) * 16 + ptl;     // 0..63
        const int quad = lane & 1;
        int nb[16];
        {
            const int4* q = (const int4*)(s_nbr + pt_p * 16);
            int4 n0 = q[0], n1 = q[1], n2 = q[2], n3 = q[3];
            nb[0]=n0.x; nb[1]=n0.y; nb[2]=n0.z; nb[3]=n0.w;
            nb[4]=n1.x; nb[5]=n1.y; nb[6]=n1.z; nb[7]=n1.w;
            nb[8]=n2.x; nb[9]=n2.y; nb[10]=n2.z; nb[11]=n2.w;
            nb[12]=n3.x; nb[13]=n3.y; nb[14]=n3.z; nb[15]=n3.w;
        }
        const float* wp_p = s_w + pt_p * WSTR;

        for (int ci = 0; ci < NCHUNK; ++ci) {
            const int b = ci & 1;
            if (ci >= 2) NBAR_SYNC(3 + b, 384);

            const int cbase = ci * 8 + quad * 4;
            ull pa[16];
#pragma unroll
            for (int i = 0; i < 16; ++i) pa[i] = 0ULL;
            if (cbase < CIN3) {
                const float* fp = fcat + cbase;
#pragma unroll
                for (int k = 0; k < 16; ++k) {
                    float4 f4 = __ldg((const float4*)(fp + (size_t)nb[k] * STRIDE_IN));
                    ulonglong2 w01 = *(const ulonglong2*)(wp_p + k * 8);
                    ulonglong2 w23 = *(const ulonglong2*)(wp_p + k * 8 + 4);
                    ull f0 = dup2(f4.x), f1 = dup2(f4.y), f2 = dup2(f4.z), f3 = dup2(f4.w);
                    pa[0]  = ffma2(f0, w01.x, pa[0]);
                    pa[1]  = ffma2(f0, w01.y, pa[1]);
                    pa[2]  = ffma2(f0, w23.x, pa[2]);
                    pa[3]  = ffma2(f0, w23.y, pa[3]);
                    pa[4]  = ffma2(f1, w01.x, pa[4]);
                    pa[5]  = ffma2(f1, w01.y, pa[5]);
                    pa[6]  = ffma2(f1, w23.x, pa[6]);
                    pa[7]  = ffma2(f1, w23.y, pa[7]);
                    pa[8]  = ffma2(f2, w01.x, pa[8]);
                    pa[9]  = ffma2(f2, w01.y, pa[9]);
                    pa[10] = ffma2(f2, w23.x, pa[10]);
                    pa[11] = ffma2(f2, w23.y, pa[11]);
                    pa[12] = ffma2(f3, w01.x, pa[12]);
                    pa[13] = ffma2(f3, w01.y, pa[13]);
                    pa[14] = ffma2(f3, w23.x, pa[14]);
                    pa[15] = ffma2(f3, w23.y, pa[15]);
                }
            }
            uint32_t hiw[16], low[16];
#pragma unroll
            for (int g2 = 0; g2 < 2; ++g2) {
#pragma unroll
                for (int mp = 0; mp < 4; ++mp) {
                    float2 va = unpk(pa[g2 * 8 + mp]);
                    float2 vb = unpk(pa[g2 * 8 + 4 + mp]);
                    float ha0 = bf16r(va.x), ha1 = bf16r(va.y);
                    float hb0 = bf16r(vb.x), hb1 = bf16r(vb.y);
                    hiw[g2 * 8 + mp * 2 + 0] = pack_bf16(ha0, ha1);
                    hiw[g2 * 8 + mp * 2 + 1] = pack_bf16(hb0, hb1);
                    low[g2 * 8 + mp * 2 + 0] = pack_bf16(va.x - ha0, va.y - ha1);
                    low[g2 * 8 + mp * 2 + 1] = pack_bf16(vb.x - hb0, vb.y - hb1);
                }
            }
            uint32_t* abuf = smw + F_OFF_A + b * ACHUNK_WORDS;
            uint32_t* outp = abuf + pt_p * ROWW + quad * 16;
            ((uint4*)outp)[0] = ((uint4*)hiw)[0];
            ((uint4*)outp)[1] = ((uint4*)hiw)[1];
            ((uint4*)outp)[2] = ((uint4*)hiw)[2];
            ((uint4*)outp)[3] = ((uint4*)hiw)[3];
            uint32_t* outl = outp + 2560;
            ((uint4*)outl)[0] = ((uint4*)low)[0];
            ((uint4*)outl)[1] = ((uint4*)low)[1];
            ((uint4*)outl)[2] = ((uint4*)low)[2];
            ((uint4*)outl)[3] = ((uint4*)low)[3];

            __threadfence_block();
            NBAR_ARRIVE(1 + b, 384);
        }
    } else {
        // ================= MMA warps (0-7), 256 threads =================
        const int g = lane >> 2, t = lane & 3;
        const int rt = wid & 1, ch = wid >> 1;
        const int rowA = rt * 32 + g;

        auto copy_B = [&](int ci, int bsel) {
            const uint4* srcB = (const uint4*)(gB + (size_t)ci * BCHUNK_WORDS);
            const uint32_t dB = s2u(smw + F_OFF_B + bsel * BCHUNK_WORDS);
#pragma unroll
            for (int r = 0; r < 10; ++r) {
                int i = tid + r * 256;
                cp16(dB + i * 16, srcB + i);
            }
            asm volatile("cp.async.commit_group;");
        };

        copy_B(0, 0);

        float acc[32];
#pragma unroll
        for (int i = 0; i < 32; ++i) acc[i] = 0.f;

        // register-pipelined fragments: [buf][0..3]=ah, [4..7]=al, [8..11]=bh, [12..15]=bl
        uint2 fr[2][16];

        for (int ci = 0; ci < NCHUNK; ++ci) {
            const int b = ci & 1;
            asm volatile("cp.async.wait_group 0;");
            NBAR_SYNC(1 + b, 384);          // A[b] ready + B[b] visible
            if (ci + 1 < NCHUNK) copy_B(ci + 1, b ^ 1);

            const uint32_t* sAH = smw + F_OFF_A + b * ACHUNK_WORDS;
            const uint32_t* sAL = sAH + 2560;
            const uint32_t* sB  = smw + F_OFF_B + b * BCHUNK_WORDS;

            auto load_slab = [&](int s, int buf) {
                const int off = s * 8 + 2 * t;
                fr[buf][0] = *(const uint2*)(sAH + (rowA)      * ROWW + off);
                fr[buf][1] = *(const uint2*)(sAH + (rowA + 8)  * ROWW + off);
                fr[buf][2] = *(const uint2*)(sAH + (rowA + 16) * ROWW + off);
                fr[buf][3] = *(const uint2*)(sAH + (rowA + 24) * ROWW + off);
                fr[buf][4] = *(const uint2*)(sAL + (rowA)      * ROWW + off);
                fr[buf][5] = *(const uint2*)(sAL + (rowA + 8)  * ROWW + off);
                fr[buf][6] = *(const uint2*)(sAL + (rowA + 16) * ROWW + off);
                fr[buf][7] = *(const uint2*)(sAL + (rowA + 24) * ROWW + off);
#pragma unroll
                for (int nt = 0; nt < 4; ++nt) {
                    const int brow = ch * 32 + nt * 8 + g;
                    fr[buf][8 + nt]  = *(const uint2*)(sB + brow * ROWW + off);
                    fr[buf][12 + nt] = *(const uint2*)(sB + 5120 + brow * ROWW + off);
                }
            };

            load_slab(0, 0);
            load_slab(1, 1);
#pragma unroll
            for (int s = 0; s < 4; ++s) {
                const int buf = s & 1;
                uint2 ah0 = fr[buf][0], ah1 = fr[buf][1], ah2 = fr[buf][2], ah3 = fr[buf][3];
                uint2 al0 = fr[buf][4], al1 = fr[buf][5], al2 = fr[buf][6], al3 = fr[buf][7];
                uint2 bh0 = fr[buf][8], bh1 = fr[buf][9], bh2 = fr[buf][10], bh3 = fr[buf][11];
                uint2 bl0 = fr[buf][12], bl1 = fr[buf][13], bl2 = fr[buf][14], bl3 = fr[buf][15];
                if (s + 2 < 4) load_slab(s + 2, buf);   // prefetch into freed buffer
                mma_bf16(acc + 0,  ah0.x, ah1.x, ah0.y, ah1.y, bh0.x, bh0.y);
                mma_bf16(acc + 16, ah2.x, ah3.x, ah2.y, ah3.y, bh0.x, bh0.y);
                mma_bf16(acc + 4,  ah0.x, ah1.x, ah0.y, ah1.y, bh1.x, bh1.y);
                mma_bf16(acc + 20, ah2.x, ah3.x, ah2.y, ah3.y, bh1.x, bh1.y);
                mma_bf16(acc + 8,  ah0.x, ah1.x, ah0.y, ah1.y, bh2.x, bh2.y);
                mma_bf16(acc + 24, ah2.x, ah3.x, ah2.y, ah3.y, bh2.x, bh2.y);
                mma_bf16(acc + 12, ah0.x, ah1.x, ah0.y, ah1.y, bh3.x, bh3.y);
                mma_bf16(acc + 28, ah2.x, ah3.x, ah2.y, ah3.y, bh3.x, bh3.y);
                mma_bf16(acc + 0,  ah0.x, ah1.x, ah0.y, ah1.y, bl0.x, bl0.y);
                mma_bf16(acc + 16, ah2.x, ah3.x, ah2.y, ah3.y, bl0.x, bl0.y);
                mma_bf16(acc + 4,  ah0.x, ah1.x, ah0.y, ah1.y, bl1.x, bl1.y);
                mma_bf16(acc + 20, ah2.x, ah3.x, ah2.y, ah3.y, bl1.x, bl1.y);
                mma_bf16(acc + 8,  ah0.x, ah1.x, ah0.y, ah1.y, bl2.x, bl2.y);
                mma_bf16(acc + 24, ah2.x, ah3.x, ah2.y, ah3.y, bl2.x, bl2.y);
                mma_bf16(acc + 12, ah0.x, ah1.x, ah0.y, ah1.y, bl3.x, bl3.y);
                mma_bf16(acc + 28, ah2.x, ah3.x, ah2.y, ah3.y, bl3.x, bl3.y);
                mma_bf16(acc + 0,  al0.x, al1.x, al0.y, al1.y, bh0.x, bh0.y);
                mma_bf16(acc + 16, al2.x, al3.x, al2.y, al3.y, bh0.x, bh0.y);
                mma_bf16(acc + 4,  al0.x, al1.x, al0.y, al1.y, bh1.x, bh1.y);
                mma_bf16(acc + 20, al2.x, al3.x, al2.y, al3.y, bh1.x, bh1.y);
                mma_bf16(acc + 8,  al0.x, al1.x, al0.y, al1.y, bh2.x, bh2.y);
                mma_bf16(acc + 24, al2.x, al3.x, al2.y, al3.y, bh2.x, bh2.y);
                mma_bf16(acc + 12, al0.x, al1.x, al0.y, al1.y, bh3.x, bh3.y);
                mma_bf16(acc + 28, al2.x, al3.x, al2.y, al3.y, bh3.x, bh3.y);
            }
            NBAR_ARRIVE(3 + b, 384);
        }

        // epilogue: bias + leaky
#pragma unroll
        for (int mt = 0; mt < 2; ++mt) {
            const int r0 = base + rt * 32 + mt * 16 + g;
#pragma unroll
            for (int nt = 0; nt < 4; ++nt) {
                const int col = ch * 32 + nt * 8 + 2 * t;
                float b0 = s_bias[col], b1 = s_bias[col + 1];
                const float* C = acc + mt * 16 + nt * 4;
                float2 r01 = make_float2(lrelu(C[0] + b0), lrelu(C[1] + b1));
                float2 r23 = make_float2(lrelu(C[2] + b0), lrelu(C[3] + b1));
                *(float2*)(out + (size_t)r0 * OUT_STRIDE + col) = r01;
                *(float2*)(out + (size_t)(r0 + 8) * OUT_STRIDE + col) = r23;
            }
        }
    }
}

// ---------------- MLP head ----------------------------------------------------------
__global__ void mlp_kernel(const float* __restrict__ w_last, const float* __restrict__ b1,
                           const float* __restrict__ b2, const float* __restrict__ blast,
                           float* __restrict__ out) {
    __shared__ float s_f[16 * 128];
    __shared__ float s_h1[16 * 128];
    __shared__ float s_h2[16 * 64];
    const int tid = threadIdx.x;
    const int p0  = blockIdx.x * 16;

    for (int i = tid; i < 16 * 128; i += 256) s_f[i] = g_f2[(size_t)p0 * 128 + i];
    __syncthreads();
    {
        int o = tid & 127, tg = tid >> 7;
        float acc[8];
#pragma unroll
        for (int i = 0; i < 8; ++i) acc[i] = 0.f;
        for (int c = 0; c < 128; ++c) {
            float wv = g_w1t[c * 128 + o];
#pragma unroll
            for (int i = 0; i < 8; ++i) acc[i] += s_f[(tg * 8 + i) * 128 + c] * wv;
        }
        float bb = b1[o];
#pragma unroll
        for (int i = 0; i < 8; ++i) s_h1[(tg * 8 + i) * 128 + o] = lrelu(acc[i] + bb);
    }
    __syncthreads();
    {
        int jj = tid & 63, tg = tid >> 6;
        float acc[4];
#pragma unroll
        for (int i = 0; i < 4; ++i) acc[i] = 0.f;
        for (int c = 0; c < 128; ++c) {
            float wv = g_w2t[c * 64 + jj];
#pragma unroll
            for (int i = 0; i < 4; ++i) acc[i] += s_h1[(tg * 4 + i) * 128 + c] * wv;
        }
        float bb = b2[jj];
#pragma unroll
        for (int i = 0; i < 4; ++i) s_h2[(tg * 4 + i) * 64 + jj] = lrelu(acc[i] + bb);
    }
    __syncthreads();

    const int b = p0 >> 13, n0 = p0 & (NPTS - 1);
    for (int i = tid; i < 16 * 64; i += 256) {
        int t2 = i & 15, jj = i >> 4;
        out[((size_t)(b * 64 + jj)) * NPTS + n0 + t2] = s_h2[t2 * 64 + jj];
    }
    if (tid < 48) {
        int t2 = tid & 15, d = tid >> 4;
        float acc = 0.f;
#pragma unroll 8
        for (int jj = 0; jj < 64; ++jj) acc += w_last[d * 64 + jj] * s_h2[t2 * 64 + jj];
        out[(size_t)BATCH * 64 * NPTS + ((size_t)(b * 3 + d)) * NPTS + n0 + t2] = acc + blast[d];
    }
}

// ---------------- launch --------------------------------------------------------------
extern "C" void kernel_launch(void* const* d_in, const int* in_sizes, int n_in,
                              void* d_out, int out_size) {
    const float* xyz    = (const float*)d_in[0];
    const float* feat   = (const float*)d_in[1];
    const int*   knn    = (const int*)d_in[2];
    const float* w_wn1  = (const float*)d_in[3];
    const float* b_wn1  = (const float*)d_in[4];
    const float* w_lin1 = (const float*)d_in[5];
    const float* b_lin1 = (const float*)d_in[6];
    const float* w_wn2  = (const float*)d_in[7];
    const float* b_wn2  = (const float*)d_in[8];
    const float* w_lin2 = (const float*)d_in[9];
    const float* b_lin2 = (const float*)d_in[10];
    const float* w_mlp1 = (const float*)d_in[11];
    const float* b_mlp1 = (const float*)d_in[12];
    const float* w_mlp2 = (const float*)d_in[13];
    const float* b_mlp2 = (const float*)d_in[14];
    const float* w_last = (const float*)d_in[15];
    const float* b_last = (const float*)d_in[16];
    float* out = (float*)d_out;

    void *p_fcat1, *p_fcat2, *p_f2, *p_B1, *p_B2;
    cudaGetSymbolAddress(&p_fcat1, g_fcat1);
    cudaGetSymbolAddress(&p_fcat2, g_fcat2);
    cudaGetSymbolAddress(&p_f2, g_f2);
    cudaGetSymbolAddress(&p_B1, g_B1);
    cudaGetSymbolAddress(&p_B2, g_B2);

    {
        dim3 tb(32, 32);
        dim3 tg(NPTS / 32, 256 / 32, BATCH);
        transpose_feat<<<tg, tb>>>(feat);
    }
    prep_all<<<(NCH1 * BCHUNK_WORDS + 255) / 256, 256>>>(xyz, w_lin1, w_lin2, w_mlp1, w_mlp2);

    cudaFuncSetAttribute(conv_fused<256, 260, 132, NCH1>,
                         cudaFuncAttributeMaxDynamicSharedMemorySize, F_DYN_BYTES);
    conv_fused<256, 260, 132, NCH1><<<NP_TOTAL / 64, 384, F_DYN_BYTES>>>(
        (const float*)p_fcat1, knn, w_wn1, b_wn1, b_lin1, (const uint32_t*)p_B1,
        (float*)p_fcat2);

    cudaFuncSetAttribute(conv_fused<128, 132, 128, NCH2>,
                         cudaFuncAttributeMaxDynamicSharedMemorySize, F_DYN_BYTES);
    conv_fused<128, 132, 128, NCH2><<<NP_TOTAL / 64, 384, F_DYN_BYTES>>>(
        (const float*)p_fcat2, knn, w_wn2, b_wn2, b_lin2, (const uint32_t*)p_B2,
        (float*)p_f2);

    mlp_kernel<<<NP_TOTAL / 16, 256>>>(w_last, b_mlp1, b_mlp2, b_last, out);
}